// round 17
// baseline (speedup 1.0000x reference)
#include <cuda_runtime.h>
#include <cuda_pipeline.h>
#include <math.h>

#define VOCAB   50257
#define DIM     512
#define MAXDEP  20
#define CHUNK   5
#define NCHUNK  (MAXDEP / CHUNK)       // 4 chunk-CTAs per token
#define NTOK    8192                   // B*S
#define NBLK    (NTOK * NCHUNK)        // 32768 single-warp CTAs
#define PSTAGE  3                      // cp.async ring depth

__device__ float        g_partials[NBLK];
__device__ unsigned int g_count = 0;   // self-resets -> graph-replay safe

__global__ void __launch_bounds__(32) hs_kernel(
    const float* __restrict__ hidden,      // [NTOK, DIM]
    const float* __restrict__ node_emb,    // [VOCAB-1, DIM]
    const float* __restrict__ path_signs,  // [VOCAB, MAXDEP]
    const int*   __restrict__ targets,     // [NTOK]
    const int*   __restrict__ path_nodes,  // [VOCAB, MAXDEP]
    const int*   __restrict__ path_lens,   // [VOCAB]
    float*       __restrict__ out)
{
    __shared__ __align__(16) float s_rows[PSTAGE][DIM];   // 6 KB

    const int lane  = threadIdx.x;          // 32-thread CTA = one warp
    const int bid   = blockIdx.x;
    const int tok   = bid >> 2;             // token index
    const int d0    = (bid & 3) * CHUNK;    // first depth of this chunk

    const int t   = targets[tok];
    int       len = path_lens[t];
    if (len < 1) len = 1;

    float nll = 0.0f;

    if (d0 < len) {
        const int nd = min(len - d0, CHUNK);   // 1..5, warp-uniform

        // Chunk-local path metadata (lanes 0..4), broadcast via shfl.
        int   my_node = 0;
        float my_sign = 1.0f;
        if (lane < CHUNK) {
            my_node = path_nodes[(size_t)t * MAXDEP + d0 + lane];
            my_sign = (path_signs[(size_t)t * MAXDEP + d0 + lane] >= 0.0f)
                          ? 1.0f : -1.0f;
        }

        // ---- Prologue: stage rows 0..2 (clamped to nd-1 -> always valid).
        #pragma unroll
        for (int k = 0; k < PSTAGE; ++k) {
            const int dc   = (k < nd) ? k : (nd - 1);
            const int node = __shfl_sync(0xffffffffu, my_node, dc);
            const float4* g =
                reinterpret_cast<const float4*>(node_emb + (size_t)node * DIM);
            float4* s = reinterpret_cast<float4*>(&s_rows[k][0]);
            #pragma unroll
            for (int j = 0; j < 4; ++j)
                __pipeline_memcpy_async(&s[lane + 32 * j], &g[lane + 32 * j], 16);
            __pipeline_commit();
        }

        // Hidden row loads overlap the staged cp.asyncs.
        const float4* h4 =
            reinterpret_cast<const float4*>(hidden + (size_t)tok * DIM);
        const float4 h0 = h4[lane];
        const float4 h1 = h4[lane + 32];
        const float4 h2 = h4[lane + 64];
        const float4 h3 = h4[lane + 96];

        int slot = 0;
        for (int i = 0; i < nd; ++i) {
            __pipeline_wait_prior(PSTAGE - 1);
            __syncwarp();

            const float4* w4 = reinterpret_cast<const float4*>(&s_rows[slot][0]);
            const float4 w0 = w4[lane];
            const float4 w1 = w4[lane + 32];
            const float4 w2 = w4[lane + 64];
            const float4 w3 = w4[lane + 96];

            // Refill this slot for chunk-local row i+PSTAGE (clamped).
            {
                const int dc   = (i + PSTAGE < nd) ? (i + PSTAGE) : (nd - 1);
                const int node = __shfl_sync(0xffffffffu, my_node, dc);
                const float4* g =
                    reinterpret_cast<const float4*>(node_emb + (size_t)node * DIM);
                float4* s = reinterpret_cast<float4*>(&s_rows[slot][0]);
                #pragma unroll
                for (int j = 0; j < 4; ++j)
                    __pipeline_memcpy_async(&s[lane + 32 * j], &g[lane + 32 * j], 16);
                __pipeline_commit();
            }

            float a;
            a = h0.x * w0.x;           a = fmaf(h0.y, w0.y, a);
            a = fmaf(h0.z, w0.z, a);   a = fmaf(h0.w, w0.w, a);
            a = fmaf(h1.x, w1.x, a);   a = fmaf(h1.y, w1.y, a);
            a = fmaf(h1.z, w1.z, a);   a = fmaf(h1.w, w1.w, a);
            a = fmaf(h2.x, w2.x, a);   a = fmaf(h2.y, w2.y, a);
            a = fmaf(h2.z, w2.z, a);   a = fmaf(h2.w, w2.w, a);
            a = fmaf(h3.x, w3.x, a);   a = fmaf(h3.y, w3.y, a);
            a = fmaf(h3.z, w3.z, a);   a = fmaf(h3.w, w3.w, a);

            #pragma unroll
            for (int off = 16; off > 0; off >>= 1)
                a += __shfl_xor_sync(0xffffffffu, a, off);

            const float sgn = __shfl_sync(0xffffffffu, my_sign, i);
            const float z   = sgn * a;
            // -log sigmoid(z) = max(-z,0) + log1p(exp(-|z|))   (stable)
            nll += fmaxf(-z, 0.0f) + log1pf(expf(-fabsf(z)));

            if (++slot == PSTAGE) slot = 0;
        }

        __pipeline_wait_prior(0);   // drain before exit
    }

    if (lane == 0) g_partials[bid] = nll;
    __threadfence();

    // Last-block-done: one warp deterministically reduces all 32768 partials.
    __shared__ unsigned int s_last;
    if (lane == 0)
        s_last = (atomicAdd(&g_count, 1u) == (unsigned)(gridDim.x - 1));
    __syncwarp();
    const unsigned last = __shfl_sync(0xffffffffu, s_last, 0);

    if (last) {
        // 8192 float4 across 32 lanes = 256 per lane; unrolled for MLP.
        const float4* p4 = reinterpret_cast<const float4*>(g_partials);
        float s = 0.0f;
        #pragma unroll 8
        for (int i = 0; i < NBLK / (32 * 4); ++i) {
            const float4 v = p4[lane + 32 * i];
            s += (v.x + v.y) + (v.z + v.w);
        }
        #pragma unroll
        for (int off = 16; off > 0; off >>= 1)
            s += __shfl_xor_sync(0xffffffffu, s, off);
        if (lane == 0) {
            out[0]  = s * (1.0f / (float)NTOK);
            g_count = 0;   // reset for next launch / graph replay
        }
    }
}

extern "C" void kernel_launch(void* const* d_in, const int* in_sizes, int n_in,
                              void* d_out, int out_size)
{
    const float* hidden     = (const float*)d_in[0];
    const float* node_emb   = (const float*)d_in[1];
    const float* path_signs = (const float*)d_in[2];
    const int*   targets    = (const int*)  d_in[3];
    const int*   path_nodes = (const int*)  d_in[4];
    const int*   path_lens  = (const int*)  d_in[5];
    float*       out        = (float*)d_out;

    hs_kernel<<<NBLK, 32>>>(hidden, node_emb, path_signs,
                            targets, path_nodes, path_lens, out);
}